// round 16
// baseline (speedup 1.0000x reference)
#include <cuda_runtime.h>
#include <cuda_bf16.h>

// loss = sum_{pos} softplus(-p)/n_pos + sum_{neg} softplus(p)/n_neg
// over 8192x8192 f32 + i32. Streaming reduction at the streaming cap.
// R15 = R14 (session-best 82.0us) + packed per-block partials:
//   stage1 publishes ONE float4 {pos, neg, cnt_bits, 0} per block
//   (1 STG.128 instead of 3 STG.32); stage2 reads 1184 LDG.128 instead of
//   3x1184 LDG.32 -> fewer serial L2 rounds on its critical path.
//   cnt travels as int bits (__int_as_float / __float_as_int); summation
//   stays in int (exact).
// All other structure identical to R14 (two kernels, PDL join).

#define NBLOCKS  1184        // 148 SMs * 8 CTAs, one full wave
#define NTHREADS 256
#define N_TOTAL  67108864    // 8192*8192
#define N_VEC4   16777216    // N_TOTAL / 4

__device__ float4 g_part[NBLOCKS];   // {pos, neg, cnt_as_int_bits, 0}

// softplus(x)  = log1p(e^{-|x|}) + max(x, 0)
// softplus(-x) = log1p(e^{-|x|}) + max(-x, 0)
// -> one EX2 + one LG2 per element regardless of label.
__device__ __forceinline__ void lane_accum(float x, int y,
                                           float& pos, float& neg, int& cnt) {
    float ax     = fabsf(x);
    float common = __logf(1.0f + __expf(-ax));
    bool  ispos  = (y != 0);
    float relu   = fmaxf(ispos ? -x : x, 0.0f);
    float v      = common + relu;
    pos += ispos ? v : 0.0f;
    neg += ispos ? 0.0f : v;
    cnt += ispos ? 1 : 0;
}

__global__ __launch_bounds__(NTHREADS)
void reduce_stage1(const float4* __restrict__ pred,
                   const int4*  __restrict__ ty) {
    float pos = 0.0f, neg = 0.0f;
    int   cnt = 0;

    // Measured-best loop shape: 2 LDG.128 per warp-iteration; chip MLP
    // comes from 64 warps/SM. Do not touch.
    const int stride = gridDim.x * blockDim.x;
    for (int i = blockIdx.x * blockDim.x + threadIdx.x; i < N_VEC4; i += stride) {
        float4 p = __ldcs(pred + i);   // streaming: touched once
        int4   y = __ldcs(ty + i);
        lane_accum(p.x, y.x, pos, neg, cnt);
        lane_accum(p.y, y.y, pos, neg, cnt);
        lane_accum(p.z, y.z, pos, neg, cnt);
        lane_accum(p.w, y.w, pos, neg, cnt);
    }

    // Block reduction (fixed tree -> deterministic)
    #pragma unroll
    for (int o = 16; o > 0; o >>= 1) {
        pos += __shfl_down_sync(0xFFFFFFFFu, pos, o);
        neg += __shfl_down_sync(0xFFFFFFFFu, neg, o);
        cnt += __shfl_down_sync(0xFFFFFFFFu, cnt, o);
    }

    __shared__ float sp[NTHREADS / 32];
    __shared__ float sn[NTHREADS / 32];
    __shared__ int   sc[NTHREADS / 32];
    int wid = threadIdx.x >> 5;
    int lid = threadIdx.x & 31;
    if (lid == 0) { sp[wid] = pos; sn[wid] = neg; sc[wid] = cnt; }
    __syncthreads();

    if (threadIdx.x == 0) {
        constexpr int NW = NTHREADS / 32;
        float bp = 0.0f, bn = 0.0f; int bc = 0;
        #pragma unroll
        for (int w = 0; w < NW; w++) { bp += sp[w]; bn += sn[w]; bc += sc[w]; }
        g_part[blockIdx.x] = make_float4(bp, bn, __int_as_float(bc), 0.0f);
    }
    __syncthreads();
    // Partials published; stage2 (PDL-gated) may proceed once all blocks
    // have triggered — its launch/ramp overlaps this grid's drain.
    cudaTriggerProgrammaticLaunchCompletion();
}

__global__ __launch_bounds__(1024)
void reduce_stage2(float* __restrict__ out) {
    // Gate on stage1 completion under PDL; documented no-op otherwise.
    cudaGridDependencySynchronize();

    float pos = 0.0f, neg = 0.0f;
    int   cnt = 0;
    for (int i = threadIdx.x; i < NBLOCKS; i += 1024) {
        float4 v = g_part[i];          // one LDG.128 per partial
        pos += v.x;
        neg += v.y;
        cnt += __float_as_int(v.z);
    }
    #pragma unroll
    for (int o = 16; o > 0; o >>= 1) {
        pos += __shfl_down_sync(0xFFFFFFFFu, pos, o);
        neg += __shfl_down_sync(0xFFFFFFFFu, neg, o);
        cnt += __shfl_down_sync(0xFFFFFFFFu, cnt, o);
    }
    __shared__ float sp[32];
    __shared__ float sn[32];
    __shared__ int   sc[32];
    int wid = threadIdx.x >> 5;
    int lid = threadIdx.x & 31;
    if (lid == 0) { sp[wid] = pos; sn[wid] = neg; sc[wid] = cnt; }
    __syncthreads();
    if (wid == 0) {
        float bp = sp[lid];
        float bn = sn[lid];
        int   bc = sc[lid];
        #pragma unroll
        for (int o = 16; o > 0; o >>= 1) {
            bp += __shfl_down_sync(0xFFFFFFFFu, bp, o);
            bn += __shfl_down_sync(0xFFFFFFFFu, bn, o);
            bc += __shfl_down_sync(0xFFFFFFFFu, bc, o);
        }
        if (lid == 0) {
            float n_pos = (float)bc;
            float n_neg = (float)(N_TOTAL - bc);
            out[0] = bp / n_pos + bn / n_neg;
        }
    }
}

extern "C" void kernel_launch(void* const* d_in, const int* in_sizes, int n_in,
                              void* d_out, int out_size) {
    const float4* pred = (const float4*)d_in[0];  // pred_y: float32 [8192,8192]
    const int4*   ty   = (const int4*)  d_in[1];  // true_y: int32   [8192,8192]
    float*        out  = (float*)d_out;

    reduce_stage1<<<NBLOCKS, NTHREADS>>>(pred, ty);

    // Stage2 with PDL so its launch/ramp overlaps stage1's drain.
    cudaLaunchConfig_t cfg = {};
    cfg.gridDim  = dim3(1, 1, 1);
    cfg.blockDim = dim3(1024, 1, 1);
    cfg.dynamicSmemBytes = 0;
    cfg.stream = 0;
    cudaLaunchAttribute attr;
    attr.id = cudaLaunchAttributeProgrammaticStreamSerialization;
    attr.val.programmaticStreamSerializationAllowed = 1;
    cfg.attrs = &attr;
    cfg.numAttrs = 1;

    cudaError_t err = cudaLaunchKernelEx(&cfg, reduce_stage2, out);
    if (err != cudaSuccess) {
        (void)cudaGetLastError();            // clear sticky error
        reduce_stage2<<<1, 1024>>>(out);     // plain fallback (stream order)
    }
}